// round 14
// baseline (speedup 1.0000x reference)
#include <cuda_runtime.h>
#include <cuda_bf16.h>
#include <cstdint>
#include <cstddef>

// ============================================================
// Problem dims (fixed for this dataset)
// ============================================================
#define BCH 8192
#define D0  1024
#define D1  2048
#define D2  1024
#define FEAT 9                    // 8 spline basis + 1 silu
#define K0 (D0*FEAT)              // 9216
#define K1 (D1*FEAT)              // 18432
#define KP0 (K0*3)                // 27648  (bf16x3 interleaved)
#define KP1 (K1*3)                // 55296

// ============================================================
// Scratch (static device globals — no runtime allocation)
// A3 slots per source k: (ah, al, ah) ; W3 slots: (wh, wh, wl)
// sum_s A3*W3 = ah*wh + al*wh + ah*wl   (3xBF16, drops al*wl ~2^-18)
// ============================================================
__device__ __nv_bfloat16 g_A0[(size_t)BCH*KP0];   // 453 MB
__device__ __nv_bfloat16 g_W0[(size_t)D1 *KP0];   // 113 MB
__device__ float         g_H1[(size_t)BCH*D1];    // 67 MB
__device__ __nv_bfloat16 g_A1[(size_t)BCH*KP1];   // 906 MB
__device__ __nv_bfloat16 g_W1[(size_t)D2 *KP1];   // 113 MB

// ============================================================
// Helpers
// ============================================================
__device__ __forceinline__ uint32_t smem_u32(const void* p) {
    uint32_t a;
    asm("{ .reg .u64 t; cvta.to.shared.u64 t, %1; cvt.u32.u64 %0, t; }" : "=r"(a) : "l"(p));
    return a;
}

__device__ __forceinline__ void cp16(uint32_t saddr, const void* gaddr) {
    asm volatile("cp.async.cg.shared.global [%0], [%1], 16;" :: "r"(saddr), "l"(gaddr));
}

__device__ __forceinline__ void ldsm_x4(uint32_t& r0, uint32_t& r1, uint32_t& r2, uint32_t& r3,
                                        uint32_t addr) {
    asm volatile("ldmatrix.sync.aligned.m8n8.x4.shared.b16 {%0,%1,%2,%3}, [%4];"
                 : "=r"(r0), "=r"(r1), "=r"(r2), "=r"(r3) : "r"(addr));
}

// split v into bf16 hi + bf16 lo
__device__ __forceinline__ void bf16_split(float v, __nv_bfloat16& h, __nv_bfloat16& l) {
    h = __float2bfloat16(v);
    l = __float2bfloat16(v - __bfloat162float(h));
}

// ============================================================
// Prep kernels: compute features / weights, write bf16x3 planes
// ============================================================

// Cox-de Boor (k=3), exact mirror of the reference recursion, + silu
__device__ __forceinline__ void kan_features(float x, const float* __restrict__ grid, float* f) {
    float t[12];
#pragma unroll
    for (int j = 0; j < 12; j++) t[j] = __ldg(grid + j);
    float Bv[11];
#pragma unroll
    for (int j = 0; j < 11; j++) Bv[j] = (x >= t[j] && x < t[j + 1]) ? 1.f : 0.f;
#pragma unroll
    for (int p = 1; p <= 3; p++) {
#pragma unroll
        for (int j = 0; j + p < 11; j++) {
            float left  = (x - t[j])         / (t[j + p]     - t[j]);
            float right = (t[j + p + 1] - x) / (t[j + p + 1] - t[j + 1]);
            Bv[j] = left * Bv[j] + right * Bv[j + 1];
        }
    }
#pragma unroll
    for (int c = 0; c < 8; c++) f[c] = Bv[c];
    f[8] = x / (1.f + expf(-x));   // silu
}

// which==0: X_ext -> g_A0 ; which==1: g_H1 -> g_A1
__global__ void prep_a_kernel(const float* __restrict__ X_ext,
                              const float* __restrict__ grid,
                              int which, int total) {
    const float* X = (which == 0) ? X_ext : g_H1;
    __nv_bfloat16* A = (which == 0) ? g_A0 : g_A1;
    for (int e = blockIdx.x * blockDim.x + threadIdx.x; e < total;
         e += gridDim.x * blockDim.x) {
        float f[FEAT];
        kan_features(X[e], grid, f);
        __nv_bfloat16* a = A + (size_t)e * (FEAT * 3);
#pragma unroll
        for (int j = 0; j < FEAT; j++) {
            __nv_bfloat16 h, l;
            bf16_split(f[j], h, l);
            a[3*j + 0] = h;   // pairs with wh
            a[3*j + 1] = l;   // pairs with wh
            a[3*j + 2] = h;   // pairs with wl
        }
    }
}

// which==0 -> g_W0 ; which==1 -> g_W1
__global__ void prep_w_kernel(const float* __restrict__ coef, const float* __restrict__ sb,
                              const float* __restrict__ sp, const float* __restrict__ mask,
                              int which, int total) {
    __nv_bfloat16* Wbase = (which == 0) ? g_W0 : g_W1;
    for (int e = blockIdx.x * blockDim.x + threadIdx.x; e < total;
         e += gridDim.x * blockDim.x) {
        __nv_bfloat16* W = Wbase + (size_t)e * (FEAT * 3);
        float m = mask[e];
        float s = sp[e] * m;
        const float* c = coef + (size_t)e * 8;
#pragma unroll
        for (int j = 0; j < FEAT; j++) {
            float v = (j < 8) ? c[j] * s : sb[e] * m;
            __nv_bfloat16 h, l;
            bf16_split(v, h, l);
            W[3*j + 0] = h;   // pairs with ah
            W[3*j + 1] = h;   // pairs with al
            W[3*j + 2] = l;   // pairs with ah
        }
    }
}

// ============================================================
// bf16 mma.sync GEMM over interleaved K' = 3K:
//   C[M,N] = A3[M,K'] * W3[N,K']^T + bias
// BM=128, BN=128, BK'=64 bf16 (128B rows, padded to 144B),
// 256 threads (4x2 warps, 32x64 warp tile), 4-stage cp.async,
// ldmatrix.x4 fragment loads + double-buffered ks pipeline.
// ============================================================
constexpr int BM = 128, BN = 128, BKP = 64;
constexpr int STAGES     = 4;
constexpr int ROW_BYTES  = 144;                   // 128B data + 16B pad
constexpr int TILE_BYTES = 128 * ROW_BYTES;       // 18432
constexpr int STG_BYTES  = 2 * TILE_BYTES;        // 36864
constexpr int GEMM_SMEM  = STAGES * STG_BYTES;    // 147456

__global__ void __launch_bounds__(256, 1)
kan_gemm_kernel(int which, const float* __restrict__ bias, float* __restrict__ Cout,
                int Ntot, int Kp)
{
    extern __shared__ char smem[];

    const __nv_bfloat16* A = (which == 0) ? g_A0 : g_A1;
    const __nv_bfloat16* W = (which == 0) ? g_W0 : g_W1;
    float*               C = (which == 0) ? g_H1 : Cout;

    const int tid  = threadIdx.x;
    const int wid  = tid >> 5, lane = tid & 31;
    const int g    = lane >> 2, t = lane & 3;      // mma quad coords
    const int warp_m = wid & 3, warp_n = wid >> 2; // 4 x 2 warp grid

    // CTA swizzle: supergroups of 8 M-tiles so a wave shares A/B tiles in L2
    const int grid_n = Ntot / BN;
    const int GROUP  = 8;
    const int ppg    = GROUP * grid_n;
    const int pid    = blockIdx.x;
    const int mt0    = (pid / ppg) * GROUP + (pid % GROUP);
    const int nt0    = (pid % ppg) / GROUP;
    const int m0     = mt0 * BM;
    const int n0     = nt0 * BN;
    const int KI     = Kp / BKP;

    const uint32_t sbase = smem_u32(smem);
    const __nv_bfloat16* gA = A + (size_t)m0 * Kp;
    const __nv_bfloat16* gB = W + (size_t)n0 * Kp;

    // ---- lane-constant ldmatrix offsets ----
    // A (16x16 tile): mat = lane>>3 ; row = (mat&1)*8 + lane&7 ; colHalf = mat>>1
    const int aRow   = (((lane >> 3) & 1) << 3) + (lane & 7);
    const int aColH  = lane >> 4;
    // B (two n8 tiles per x4): nSel = lane>>4 ; kHalf = (lane>>3)&1 ; row = lane&7
    const int bNSel  = lane >> 4;
    const int bKHalf = (lane >> 3) & 1;
    const int bRow   = lane & 7;

    uint32_t aOff[2], bOff[4];
#pragma unroll
    for (int mt = 0; mt < 2; mt++)
        aOff[mt] = (uint32_t)((warp_m * 32 + mt * 16 + aRow) * ROW_BYTES + aColH * 16);
#pragma unroll
    for (int q = 0; q < 4; q++)
        bOff[q] = (uint32_t)(TILE_BYTES +
                  (warp_n * 64 + (2 * q + bNSel) * 8 + bRow) * ROW_BYTES + bKHalf * 16);

    auto load_stage = [&](int s, int kt) {
        uint32_t as = sbase + (uint32_t)(s * STG_BYTES);
        uint32_t bs = as + (uint32_t)TILE_BYTES;
        const __nv_bfloat16* a = gA + (size_t)kt * BKP;
        const __nv_bfloat16* b = gB + (size_t)kt * BKP;
#pragma unroll
        for (int it = 0; it < 4; it++) {           // A: 128 rows x 8 x 16B
            int c = tid + it * 256;
            int r = c >> 3, ch = c & 7;
            cp16(as + (uint32_t)(r * ROW_BYTES + ch * 16), a + (size_t)r * Kp + ch * 8);
        }
#pragma unroll
        for (int it = 0; it < 4; it++) {           // B: 128 rows x 8 x 16B
            int c = tid + it * 256;
            int r = c >> 3, ch = c & 7;
            cp16(bs + (uint32_t)(r * ROW_BYTES + ch * 16), b + (size_t)r * Kp + ch * 8);
        }
        asm volatile("cp.async.commit_group;" ::: "memory");
    };

    float acc[2][8][4];
#pragma unroll
    for (int mt = 0; mt < 2; mt++)
#pragma unroll
        for (int nt = 0; nt < 8; nt++)
#pragma unroll
            for (int i = 0; i < 4; i++) acc[mt][nt][i] = 0.f;

    // fragment double buffers
    uint32_t afr[2][2][4], bfr[2][8][2];

    // prologue: 3 stages in flight
    for (int s = 0; s < 3; s++) load_stage(s, s);

    for (int ki = 0; ki < KI; ki++) {
        if (ki < KI - 2)        asm volatile("cp.async.wait_group 2;" ::: "memory");
        else if (ki == KI - 2)  asm volatile("cp.async.wait_group 1;" ::: "memory");
        else                    asm volatile("cp.async.wait_group 0;" ::: "memory");
        __syncthreads();   // stage ki visible; all warps past compute(ki-1)

        if (ki + 3 < KI) load_stage((ki + 3) & 3, ki + 3);  // overwrites stage (ki-1)&3

        const uint32_t stg = sbase + (uint32_t)((ki & 3) * STG_BYTES);

        // load fragments for ks=0
#pragma unroll
        for (int mt = 0; mt < 2; mt++)
            ldsm_x4(afr[0][mt][0], afr[0][mt][1], afr[0][mt][2], afr[0][mt][3],
                    stg + aOff[mt]);
#pragma unroll
        for (int q = 0; q < 4; q++)
            ldsm_x4(bfr[0][2*q][0], bfr[0][2*q][1], bfr[0][2*q+1][0], bfr[0][2*q+1][1],
                    stg + bOff[q]);

#pragma unroll
        for (int ks = 0; ks < 4; ks++) {           // 4 x k16 steps over BK'=64
            const int cur = ks & 1, nxt = cur ^ 1;
            if (ks < 3) {
                const uint32_t ko = (uint32_t)((ks + 1) * 32);
#pragma unroll
                for (int mt = 0; mt < 2; mt++)
                    ldsm_x4(afr[nxt][mt][0], afr[nxt][mt][1], afr[nxt][mt][2], afr[nxt][mt][3],
                            stg + aOff[mt] + ko);
#pragma unroll
                for (int q = 0; q < 4; q++)
                    ldsm_x4(bfr[nxt][2*q][0], bfr[nxt][2*q][1],
                            bfr[nxt][2*q+1][0], bfr[nxt][2*q+1][1],
                            stg + bOff[q] + ko);
            }
#pragma unroll
            for (int mt = 0; mt < 2; mt++)
#pragma unroll
                for (int nt = 0; nt < 8; nt++)
                    asm volatile(
                        "mma.sync.aligned.m16n8k16.row.col.f32.bf16.bf16.f32 "
                        "{%0,%1,%2,%3}, {%4,%5,%6,%7}, {%8,%9}, {%0,%1,%2,%3};"
                        : "+f"(acc[mt][nt][0]), "+f"(acc[mt][nt][1]),
                          "+f"(acc[mt][nt][2]), "+f"(acc[mt][nt][3])
                        : "r"(afr[cur][mt][0]), "r"(afr[cur][mt][1]),
                          "r"(afr[cur][mt][2]), "r"(afr[cur][mt][3]),
                          "r"(bfr[cur][nt][0]), "r"(bfr[cur][nt][1]));
        }
    }

    // ---- epilogue: direct float2 stores + bias ----
#pragma unroll
    for (int mt = 0; mt < 2; mt++) {
        const int r0 = m0 + warp_m * 32 + mt * 16 + g;
#pragma unroll
        for (int nt = 0; nt < 8; nt++) {
            const int col = n0 + warp_n * 64 + nt * 8 + 2 * t;
            const float2 b2 = *(const float2*)(bias + col);
            float2 v0 = make_float2(acc[mt][nt][0] + b2.x, acc[mt][nt][1] + b2.y);
            float2 v1 = make_float2(acc[mt][nt][2] + b2.x, acc[mt][nt][3] + b2.y);
            *(float2*)(C + (size_t)r0 * Ntot + col)       = v0;
            *(float2*)(C + (size_t)(r0 + 8) * Ntot + col) = v1;
        }
    }
}

// ============================================================
// Launch
// ============================================================
extern "C" void kernel_launch(void* const* d_in, const int* in_sizes, int n_in,
                              void* d_out, int out_size) {
    const float* x     = (const float*)d_in[0];
    const float* coef0 = (const float*)d_in[1];
    const float* sb0   = (const float*)d_in[2];
    const float* sp0   = (const float*)d_in[3];
    const float* mask0 = (const float*)d_in[4];
    const float* bias0 = (const float*)d_in[5];
    const float* coef1 = (const float*)d_in[6];
    const float* sb1   = (const float*)d_in[7];
    const float* sp1   = (const float*)d_in[8];
    const float* mask1 = (const float*)d_in[9];
    const float* bias1 = (const float*)d_in[10];
    const float* grid  = (const float*)d_in[11];
    float* out = (float*)d_out;

    cudaFuncSetAttribute(kan_gemm_kernel, cudaFuncAttributeMaxDynamicSharedMemorySize, GEMM_SMEM);

    // weight prep (bf16x3 planes)
    prep_w_kernel<<<2048, 512>>>(coef0, sb0, sp0, mask0, 0, D1 * D0);
    prep_w_kernel<<<2048, 512>>>(coef1, sb1, sp1, mask1, 1, D2 * D1);
    // layer 0 features
    prep_a_kernel<<<2048, 512>>>(x, grid, 0, BCH * D0);
    // GEMM1: H1 = A0 * W0^T + bias0   (M=8192, N=2048, K'=27648)
    {
        int blocks = (BCH / BM) * (D1 / BN);    // 1024
        kan_gemm_kernel<<<blocks, 256, GEMM_SMEM>>>(0, bias0, nullptr, D1, KP0);
    }
    // layer 1 features
    prep_a_kernel<<<4096, 512>>>(nullptr, grid, 1, BCH * D1);
    // GEMM2: out = A1 * W1^T + bias1  (M=8192, N=1024, K'=55296)
    {
        int blocks = (BCH / BM) * (D2 / BN);    // 512
        kan_gemm_kernel<<<blocks, 256, GEMM_SMEM>>>(1, bias1, out, D2, KP1);
    }
}

// round 15
// speedup vs baseline: 1.1427x; 1.1427x over previous
#include <cuda_runtime.h>
#include <cuda_bf16.h>
#include <cstdint>
#include <cstddef>

// ============================================================
// Problem dims (fixed for this dataset)
// ============================================================
#define BCH 8192
#define D0  1024
#define D1  2048
#define D2  1024
#define FEAT 9                    // 8 spline basis + 1 silu
#define K0 (D0*FEAT)              // 9216
#define K1 (D1*FEAT)              // 18432
#define KP0 (K0*3)                // 27648  (bf16x3 interleaved)
#define KP1 (K1*3)                // 55296

// ============================================================
// Scratch (static device globals — no runtime allocation)
// A3 slots per source k: (ah, al, ah) ; W3 slots: (wh, wh, wl)
// sum_s A3*W3 = ah*wh + al*wh + ah*wl   (3xBF16, drops al*wl ~2^-18)
// ============================================================
__device__ __nv_bfloat16 g_A0[(size_t)BCH*KP0];   // 453 MB
__device__ __nv_bfloat16 g_W0[(size_t)D1 *KP0];   // 113 MB
__device__ float         g_H1[(size_t)BCH*D1];    // 67 MB
__device__ __nv_bfloat16 g_A1[(size_t)BCH*KP1];   // 906 MB
__device__ __nv_bfloat16 g_W1[(size_t)D2 *KP1];   // 113 MB

// ============================================================
// Helpers
// ============================================================
__device__ __forceinline__ uint32_t smem_u32(const void* p) {
    uint32_t a;
    asm("{ .reg .u64 t; cvta.to.shared.u64 t, %1; cvt.u32.u64 %0, t; }" : "=r"(a) : "l"(p));
    return a;
}

__device__ __forceinline__ void cp16(uint32_t saddr, const void* gaddr) {
    asm volatile("cp.async.cg.shared.global [%0], [%1], 16;" :: "r"(saddr), "l"(gaddr));
}

__device__ __forceinline__ void ldsm_x4(uint32_t& r0, uint32_t& r1, uint32_t& r2, uint32_t& r3,
                                        uint32_t addr) {
    asm volatile("ldmatrix.sync.aligned.m8n8.x4.shared.b16 {%0,%1,%2,%3}, [%4];"
                 : "=r"(r0), "=r"(r1), "=r"(r2), "=r"(r3) : "r"(addr));
}

// split v into bf16 hi + bf16 lo
__device__ __forceinline__ void bf16_split(float v, __nv_bfloat16& h, __nv_bfloat16& l) {
    h = __float2bfloat16(v);
    l = __float2bfloat16(v - __bfloat162float(h));
}

// ============================================================
// Prep kernels: compute features / weights, write bf16x3 planes
// ============================================================

// Cox-de Boor (k=3), exact mirror of the reference recursion, + silu
__device__ __forceinline__ void kan_features(float x, const float* __restrict__ grid, float* f) {
    float t[12];
#pragma unroll
    for (int j = 0; j < 12; j++) t[j] = __ldg(grid + j);
    float Bv[11];
#pragma unroll
    for (int j = 0; j < 11; j++) Bv[j] = (x >= t[j] && x < t[j + 1]) ? 1.f : 0.f;
#pragma unroll
    for (int p = 1; p <= 3; p++) {
#pragma unroll
        for (int j = 0; j + p < 11; j++) {
            float left  = (x - t[j])         / (t[j + p]     - t[j]);
            float right = (t[j + p + 1] - x) / (t[j + p + 1] - t[j + 1]);
            Bv[j] = left * Bv[j] + right * Bv[j + 1];
        }
    }
#pragma unroll
    for (int c = 0; c < 8; c++) f[c] = Bv[c];
    f[8] = x / (1.f + expf(-x));   // silu
}

// which==0: X_ext -> g_A0 ; which==1: g_H1 -> g_A1
__global__ void prep_a_kernel(const float* __restrict__ X_ext,
                              const float* __restrict__ grid,
                              int which, int total) {
    const float* X = (which == 0) ? X_ext : g_H1;
    __nv_bfloat16* A = (which == 0) ? g_A0 : g_A1;
    for (int e = blockIdx.x * blockDim.x + threadIdx.x; e < total;
         e += gridDim.x * blockDim.x) {
        float f[FEAT];
        kan_features(X[e], grid, f);
        __nv_bfloat16* a = A + (size_t)e * (FEAT * 3);
#pragma unroll
        for (int j = 0; j < FEAT; j++) {
            __nv_bfloat16 h, l;
            bf16_split(f[j], h, l);
            a[3*j + 0] = h;   // pairs with wh
            a[3*j + 1] = l;   // pairs with wh
            a[3*j + 2] = h;   // pairs with wl
        }
    }
}

// which==0 -> g_W0 ; which==1 -> g_W1
__global__ void prep_w_kernel(const float* __restrict__ coef, const float* __restrict__ sb,
                              const float* __restrict__ sp, const float* __restrict__ mask,
                              int which, int total) {
    __nv_bfloat16* Wbase = (which == 0) ? g_W0 : g_W1;
    for (int e = blockIdx.x * blockDim.x + threadIdx.x; e < total;
         e += gridDim.x * blockDim.x) {
        __nv_bfloat16* W = Wbase + (size_t)e * (FEAT * 3);
        float m = mask[e];
        float s = sp[e] * m;
        const float* c = coef + (size_t)e * 8;
#pragma unroll
        for (int j = 0; j < FEAT; j++) {
            float v = (j < 8) ? c[j] * s : sb[e] * m;
            __nv_bfloat16 h, l;
            bf16_split(v, h, l);
            W[3*j + 0] = h;   // pairs with ah
            W[3*j + 1] = h;   // pairs with al
            W[3*j + 2] = l;   // pairs with ah
        }
    }
}

// ============================================================
// bf16 mma.sync GEMM over interleaved K' = 3K:
//   C[M,N] = A3[M,K'] * W3[N,K']^T + bias
// BM=128, BN=128, BK'=64 bf16 (128B rows, padded to 144B),
// 256 threads (4x2 warps, 32x64 warp tile), 3-stage cp.async,
// ldmatrix.x4 fragment loads, 2 CTAs/SM (128 regs/thread).
// ============================================================
constexpr int BM = 128, BN = 128, BKP = 64;
constexpr int STAGES     = 3;
constexpr int ROW_BYTES  = 144;                   // 128B data + 16B pad
constexpr int TILE_BYTES = 128 * ROW_BYTES;       // 18432
constexpr int STG_BYTES  = 2 * TILE_BYTES;        // 36864
constexpr int GEMM_SMEM  = STAGES * STG_BYTES;    // 110592 -> 2 CTAs/SM

__global__ void __launch_bounds__(256, 2)
kan_gemm_kernel(int which, const float* __restrict__ bias, float* __restrict__ Cout,
                int Ntot, int Kp)
{
    extern __shared__ char smem[];

    const __nv_bfloat16* A = (which == 0) ? g_A0 : g_A1;
    const __nv_bfloat16* W = (which == 0) ? g_W0 : g_W1;
    float*               C = (which == 0) ? g_H1 : Cout;

    const int tid  = threadIdx.x;
    const int wid  = tid >> 5, lane = tid & 31;
    const int g    = lane >> 2, t = lane & 3;      // mma quad coords
    const int warp_m = wid & 3, warp_n = wid >> 2; // 4 x 2 warp grid

    // CTA swizzle: supergroups of 8 M-tiles so a wave shares A/B tiles in L2
    const int grid_n = Ntot / BN;
    const int GROUP  = 8;
    const int ppg    = GROUP * grid_n;
    const int pid    = blockIdx.x;
    const int mt0    = (pid / ppg) * GROUP + (pid % GROUP);
    const int nt0    = (pid % ppg) / GROUP;
    const int m0     = mt0 * BM;
    const int n0     = nt0 * BN;
    const int KI     = Kp / BKP;

    const uint32_t sbase = smem_u32(smem);
    const __nv_bfloat16* gA = A + (size_t)m0 * Kp;
    const __nv_bfloat16* gB = W + (size_t)n0 * Kp;

    // ---- lane-constant ldmatrix offsets ----
    const int aRow   = (((lane >> 3) & 1) << 3) + (lane & 7);
    const int aColH  = lane >> 4;
    const int bNSel  = lane >> 4;
    const int bKHalf = (lane >> 3) & 1;
    const int bRow   = lane & 7;

    uint32_t aOff[2], bOff[4];
#pragma unroll
    for (int mt = 0; mt < 2; mt++)
        aOff[mt] = (uint32_t)((warp_m * 32 + mt * 16 + aRow) * ROW_BYTES + aColH * 16);
#pragma unroll
    for (int q = 0; q < 4; q++)
        bOff[q] = (uint32_t)(TILE_BYTES +
                  (warp_n * 64 + (2 * q + bNSel) * 8 + bRow) * ROW_BYTES + bKHalf * 16);

    auto load_stage = [&](int s, int kt) {
        uint32_t as = sbase + (uint32_t)(s * STG_BYTES);
        uint32_t bs = as + (uint32_t)TILE_BYTES;
        const __nv_bfloat16* a = gA + (size_t)kt * BKP;
        const __nv_bfloat16* b = gB + (size_t)kt * BKP;
#pragma unroll
        for (int it = 0; it < 4; it++) {           // A: 128 rows x 8 x 16B
            int c = tid + it * 256;
            int r = c >> 3, ch = c & 7;
            cp16(as + (uint32_t)(r * ROW_BYTES + ch * 16), a + (size_t)r * Kp + ch * 8);
        }
#pragma unroll
        for (int it = 0; it < 4; it++) {           // B: 128 rows x 8 x 16B
            int c = tid + it * 256;
            int r = c >> 3, ch = c & 7;
            cp16(bs + (uint32_t)(r * ROW_BYTES + ch * 16), b + (size_t)r * Kp + ch * 8);
        }
        asm volatile("cp.async.commit_group;" ::: "memory");
    };

    float acc[2][8][4];
#pragma unroll
    for (int mt = 0; mt < 2; mt++)
#pragma unroll
        for (int nt = 0; nt < 8; nt++)
#pragma unroll
            for (int i = 0; i < 4; i++) acc[mt][nt][i] = 0.f;

    // prologue: 2 stages in flight
    load_stage(0, 0);
    load_stage(1, 1);

    for (int ki = 0; ki < KI; ki++) {
        if (ki < KI - 1)  asm volatile("cp.async.wait_group 1;" ::: "memory");
        else              asm volatile("cp.async.wait_group 0;" ::: "memory");
        __syncthreads();   // stage ki visible; all warps past compute(ki-1)

        if (ki + 2 < KI) load_stage((ki + 2) % STAGES, ki + 2);  // slot (ki-1)%3: consumed, safe

        const uint32_t stg = sbase + (uint32_t)((ki % STAGES) * STG_BYTES);

#pragma unroll
        for (int ks = 0; ks < 4; ks++) {           // 4 x k16 steps over BK'=64
            const uint32_t ko = (uint32_t)(ks * 32);
            uint32_t afr[2][4], bfr[8][2];
#pragma unroll
            for (int mt = 0; mt < 2; mt++)
                ldsm_x4(afr[mt][0], afr[mt][1], afr[mt][2], afr[mt][3],
                        stg + aOff[mt] + ko);
#pragma unroll
            for (int q = 0; q < 4; q++)
                ldsm_x4(bfr[2*q][0], bfr[2*q][1], bfr[2*q+1][0], bfr[2*q+1][1],
                        stg + bOff[q] + ko);
#pragma unroll
            for (int mt = 0; mt < 2; mt++)
#pragma unroll
                for (int nt = 0; nt < 8; nt++)
                    asm volatile(
                        "mma.sync.aligned.m16n8k16.row.col.f32.bf16.bf16.f32 "
                        "{%0,%1,%2,%3}, {%4,%5,%6,%7}, {%8,%9}, {%0,%1,%2,%3};"
                        : "+f"(acc[mt][nt][0]), "+f"(acc[mt][nt][1]),
                          "+f"(acc[mt][nt][2]), "+f"(acc[mt][nt][3])
                        : "r"(afr[mt][0]), "r"(afr[mt][1]),
                          "r"(afr[mt][2]), "r"(afr[mt][3]),
                          "r"(bfr[nt][0]), "r"(bfr[nt][1]));
        }
    }

    // ---- epilogue: direct float2 stores + bias ----
#pragma unroll
    for (int mt = 0; mt < 2; mt++) {
        const int r0 = m0 + warp_m * 32 + mt * 16 + g;
#pragma unroll
        for (int nt = 0; nt < 8; nt++) {
            const int col = n0 + warp_n * 64 + nt * 8 + 2 * t;
            const float2 b2 = *(const float2*)(bias + col);
            float2 v0 = make_float2(acc[mt][nt][0] + b2.x, acc[mt][nt][1] + b2.y);
            float2 v1 = make_float2(acc[mt][nt][2] + b2.x, acc[mt][nt][3] + b2.y);
            *(float2*)(C + (size_t)r0 * Ntot + col)       = v0;
            *(float2*)(C + (size_t)(r0 + 8) * Ntot + col) = v1;
        }
    }
}

// ============================================================
// Launch
// ============================================================
extern "C" void kernel_launch(void* const* d_in, const int* in_sizes, int n_in,
                              void* d_out, int out_size) {
    const float* x     = (const float*)d_in[0];
    const float* coef0 = (const float*)d_in[1];
    const float* sb0   = (const float*)d_in[2];
    const float* sp0   = (const float*)d_in[3];
    const float* mask0 = (const float*)d_in[4];
    const float* bias0 = (const float*)d_in[5];
    const float* coef1 = (const float*)d_in[6];
    const float* sb1   = (const float*)d_in[7];
    const float* sp1   = (const float*)d_in[8];
    const float* mask1 = (const float*)d_in[9];
    const float* bias1 = (const float*)d_in[10];
    const float* grid  = (const float*)d_in[11];
    float* out = (float*)d_out;

    cudaFuncSetAttribute(kan_gemm_kernel, cudaFuncAttributeMaxDynamicSharedMemorySize, GEMM_SMEM);

    // weight prep (bf16x3 planes)
    prep_w_kernel<<<2048, 512>>>(coef0, sb0, sp0, mask0, 0, D1 * D0);
    prep_w_kernel<<<2048, 512>>>(coef1, sb1, sp1, mask1, 1, D2 * D1);
    // layer 0 features
    prep_a_kernel<<<2048, 512>>>(x, grid, 0, BCH * D0);
    // GEMM1: H1 = A0 * W0^T + bias0   (M=8192, N=2048, K'=27648)
    {
        int blocks = (BCH / BM) * (D1 / BN);    // 1024
        kan_gemm_kernel<<<blocks, 256, GEMM_SMEM>>>(0, bias0, nullptr, D1, KP0);
    }
    // layer 1 features
    prep_a_kernel<<<4096, 512>>>(nullptr, grid, 1, BCH * D1);
    // GEMM2: out = A1 * W1^T + bias1  (M=8192, N=1024, K'=55296)
    {
        int blocks = (BCH / BM) * (D2 / BN);    // 512
        kan_gemm_kernel<<<blocks, 256, GEMM_SMEM>>>(1, bias1, out, D2, KP1);
    }
}